// round 2
// baseline (speedup 1.0000x reference)
#include <cuda_runtime.h>

// Problem constants
#define SEQ   2048
#define DM    768
#define NH    12
#define DH    64
#define BATCH 4
#define M_TOTAL (BATCH * SEQ)   // 8192

// Head-split projection scratch: [b, h, s, d]
__device__ float g_wq[BATCH * NH * SEQ * DH];
__device__ float g_wk[BATCH * NH * SEQ * DH];
__device__ float g_wv[BATCH * NH * SEQ * DH];

// ---------------------------------------------------------------------------
// Projection GEMM: Out[b,h,s,d] = X[m,:] . W[n,:] + bias[n]
//   X: [8192, 768] row-major, W: [768, 768] row-major (torch Linear W)
//   m = b*SEQ + s, n = h*DH + d
// Classic 128x128x8 SGEMM, 256 threads, 8x8 microtile per thread.
// ---------------------------------------------------------------------------
__global__ __launch_bounds__(256) void proj_kernel(
    const float* __restrict__ X,
    const float* __restrict__ W,
    const float* __restrict__ bias,
    float* __restrict__ Out)
{
    __shared__ float As[8][128];
    __shared__ float Bs[8][128];

    const int tid = threadIdx.x;
    const int bm = blockIdx.y * 128;
    const int bn = blockIdx.x * 128;
    const int ty = tid >> 4;         // 0..15
    const int tx = tid & 15;         // 0..15

    const int ldRow = tid >> 1;          // 0..127
    const int ldCol = (tid & 1) * 4;     // 0 or 4

    const float* Xp = X + (size_t)(bm + ldRow) * DM + ldCol;
    const float* Wp = W + (size_t)(bn + ldRow) * DM + ldCol;

    float acc[8][8];
#pragma unroll
    for (int i = 0; i < 8; i++)
#pragma unroll
        for (int j = 0; j < 8; j++) acc[i][j] = 0.f;

    for (int k0 = 0; k0 < DM; k0 += 8) {
        float4 av = *reinterpret_cast<const float4*>(Xp + k0);
        float4 bv = *reinterpret_cast<const float4*>(Wp + k0);
        As[ldCol + 0][ldRow] = av.x;
        As[ldCol + 1][ldRow] = av.y;
        As[ldCol + 2][ldRow] = av.z;
        As[ldCol + 3][ldRow] = av.w;
        Bs[ldCol + 0][ldRow] = bv.x;
        Bs[ldCol + 1][ldRow] = bv.y;
        Bs[ldCol + 2][ldRow] = bv.z;
        Bs[ldCol + 3][ldRow] = bv.w;
        __syncthreads();

#pragma unroll
        for (int kk = 0; kk < 8; kk++) {
            float a[8], b[8];
#pragma unroll
            for (int i = 0; i < 8; i++) a[i] = As[kk][ty * 8 + i];
#pragma unroll
            for (int j = 0; j < 8; j++) b[j] = Bs[kk][tx * 8 + j];
#pragma unroll
            for (int i = 0; i < 8; i++)
#pragma unroll
                for (int j = 0; j < 8; j++)
                    acc[i][j] += a[i] * b[j];
        }
        __syncthreads();
    }

    // Epilogue: add bias, scatter into head-split layout [b, h, s, d]
#pragma unroll
    for (int i = 0; i < 8; i++) {
        const int m = bm + ty * 8 + i;
        const int bidx = m / SEQ;
        const int s = m % SEQ;
#pragma unroll
        for (int j = 0; j < 8; j++) {
            const int n = bn + tx * 8 + j;
            const int h = n / DH;
            const int d = n % DH;
            Out[(((size_t)(bidx * NH + h)) * SEQ + s) * DH + d] = acc[i][j] + bias[n];
        }
    }
}

// ---------------------------------------------------------------------------
// Flash attention (fp32, no scale, no mask): one query row per thread.
//   BM = 64 query rows / block (64 threads), BN = 32 keys per tile.
//   Q row + O accumulator in registers, K/V tiles in smem (broadcast reads).
// ---------------------------------------------------------------------------
#define BM 64
#define BN 32

__global__ __launch_bounds__(BM) void flash_kernel(
    const float* __restrict__ Qh,
    const float* __restrict__ Kh,
    const float* __restrict__ Vh,
    float* __restrict__ out)
{
    __shared__ float Ks[BN][DH];
    __shared__ float Vs[BN][DH];

    const int t = threadIdx.x;
    const int b = blockIdx.z;
    const int h = blockIdx.y;
    const int row = blockIdx.x * BM + t;

    const size_t head_base = ((size_t)(b * NH + h)) * SEQ * DH;

    // Load this thread's Q row into registers (vectorized)
    float q[DH];
    {
        const float4* qsrc = reinterpret_cast<const float4*>(Qh + head_base + (size_t)row * DH);
#pragma unroll
        for (int i = 0; i < DH / 4; i++) {
            float4 v4 = qsrc[i];
            q[4 * i + 0] = v4.x;
            q[4 * i + 1] = v4.y;
            q[4 * i + 2] = v4.z;
            q[4 * i + 3] = v4.w;
        }
    }

    float o[DH];
#pragma unroll
    for (int k = 0; k < DH; k++) o[k] = 0.f;
    float m = -1e30f;
    float l = 0.f;

    const float4* Kb = reinterpret_cast<const float4*>(Kh + head_base);
    const float4* Vb = reinterpret_cast<const float4*>(Vh + head_base);
    float4* Kd = reinterpret_cast<float4*>(&Ks[0][0]);
    float4* Vd = reinterpret_cast<float4*>(&Vs[0][0]);

    for (int kb = 0; kb < SEQ; kb += BN) {
        // Cooperative tile load: BN*DH = 2048 floats = 512 float4; 8 per thread
        const float4* ksrc = Kb + (size_t)kb * (DH / 4);
        const float4* vsrc = Vb + (size_t)kb * (DH / 4);
#pragma unroll
        for (int i = 0; i < 8; i++) {
            Kd[t + 64 * i] = ksrc[t + 64 * i];
            Vd[t + 64 * i] = vsrc[t + 64 * i];
        }
        __syncthreads();

        // S = q . K_j  (32 independent accumulators, k outer for ILP)
        float s[BN];
#pragma unroll
        for (int j = 0; j < BN; j++) s[j] = 0.f;
#pragma unroll 8
        for (int k = 0; k < DH; k++) {
            float qv = q[k];
#pragma unroll
            for (int j = 0; j < BN; j++) s[j] += qv * Ks[j][k];
        }

        // Online softmax update
        float tm = s[0];
#pragma unroll
        for (int j = 1; j < BN; j++) tm = fmaxf(tm, s[j]);
        float mnew = fmaxf(m, tm);
        float corr = __expf(m - mnew);
        l *= corr;
#pragma unroll
        for (int k = 0; k < DH; k++) o[k] *= corr;
#pragma unroll
        for (int j = 0; j < BN; j++) {
            float p = __expf(s[j] - mnew);
            l += p;
            s[j] = p;
        }

        // O += P . V  (64 independent accumulators)
#pragma unroll 4
        for (int j = 0; j < BN; j++) {
            float pj = s[j];
#pragma unroll
            for (int k = 0; k < DH; k++) o[k] += pj * Vs[j][k];
        }
        m = mnew;
        __syncthreads();
    }

    // Normalize + write merged-head output [b, s, h*DH + d]
    const float inv = 1.f / l;
    float* op = out + ((size_t)(b * SEQ + row)) * DM + h * DH;
#pragma unroll
    for (int k = 0; k < DH; k += 4) {
        float4 v4;
        v4.x = o[k + 0] * inv;
        v4.y = o[k + 1] * inv;
        v4.z = o[k + 2] * inv;
        v4.w = o[k + 3] * inv;
        *reinterpret_cast<float4*>(op + k) = v4;
    }
}

// ---------------------------------------------------------------------------
// Launch
// ---------------------------------------------------------------------------
extern "C" void kernel_launch(void* const* d_in, const int* in_sizes, int n_in,
                              void* d_out, int out_size)
{
    const float* q  = (const float*)d_in[0];
    const float* k  = (const float*)d_in[1];
    const float* v  = (const float*)d_in[2];
    const float* Wq = (const float*)d_in[3];
    const float* bq = (const float*)d_in[4];
    const float* Wk = (const float*)d_in[5];
    const float* bk = (const float*)d_in[6];
    const float* Wv = (const float*)d_in[7];
    const float* bv = (const float*)d_in[8];
    float* out = (float*)d_out;

    float *dq, *dk, *dv;
    cudaGetSymbolAddress((void**)&dq, g_wq);
    cudaGetSymbolAddress((void**)&dk, g_wk);
    cudaGetSymbolAddress((void**)&dv, g_wv);

    dim3 pgrid(DM / 128, M_TOTAL / 128);   // (6, 64)
    proj_kernel<<<pgrid, 256>>>(q, Wq, bq, dq);
    proj_kernel<<<pgrid, 256>>>(k, Wk, bk, dk);
    proj_kernel<<<pgrid, 256>>>(v, Wv, bv, dv);

    dim3 agrid(SEQ / BM, NH, BATCH);       // (32, 12, 4)
    flash_kernel<<<agrid, BM>>>(dq, dk, dv, out);
}

// round 4
// speedup vs baseline: 2.2290x; 2.2290x over previous
#include <cuda_runtime.h>
#include <cstdint>

#define SEQ   2048
#define DM    768
#define NH    12
#define DH    64
#define BATCH 4
#define M_TOTAL (BATCH * SEQ)   // 8192

// Head-split projection scratch: [b, h, s, d] fp32
__device__ float g_wq[BATCH * NH * SEQ * DH];
__device__ float g_wk[BATCH * NH * SEQ * DH];
__device__ float g_wv[BATCH * NH * SEQ * DH];

// ---------------------------------------------------------------------------
// tf32 helpers
// ---------------------------------------------------------------------------
__device__ __forceinline__ float to_tf32(float x) {
    float r;
    asm("cvt.rna.tf32.f32 %0, %1;" : "=f"(r) : "f"(x));
    return r;
}

// hi/lo split for 3xTF32 emulation
__device__ __forceinline__ void split_tf32(float x, uint32_t& hi, uint32_t& lo) {
    float h = to_tf32(x);
    float l = to_tf32(x - h);
    hi = __float_as_uint(h);
    lo = __float_as_uint(l);
}

// m16n8k8 tf32 mma, C += A*B
__device__ __forceinline__ void mma8(float* c,
                                     uint32_t a0, uint32_t a1, uint32_t a2, uint32_t a3,
                                     uint32_t b0, uint32_t b1) {
    asm volatile(
        "mma.sync.aligned.m16n8k8.row.col.f32.tf32.tf32.f32 "
        "{%0,%1,%2,%3}, {%4,%5,%6,%7}, {%8,%9}, {%0,%1,%2,%3};\n"
        : "+f"(c[0]), "+f"(c[1]), "+f"(c[2]), "+f"(c[3])
        : "r"(a0), "r"(a1), "r"(a2), "r"(a3), "r"(b0), "r"(b1));
}

// ---------------------------------------------------------------------------
// Projection GEMM via tf32 mma: Out[b,h,s,d] = X[m,:] . W[n,:] + bias[n]
// BM=128, BN=64, BK=16. 256 threads = 8 warps (4m x 2n), warp tile 32x32.
// PRECISE: 3xTF32 (hi/lo emulation) for error ~2^-22/product.
// ---------------------------------------------------------------------------
template <bool PRECISE>
__global__ __launch_bounds__(256) void proj_mma_kernel(
    const float* __restrict__ X,
    const float* __restrict__ W,
    const float* __restrict__ bias,
    float* __restrict__ Out)
{
    __shared__ float Xs[128][20];   // ld=20 -> conflict-free frag loads
    __shared__ float Ws[64][20];

    const int tid  = threadIdx.x;
    const int lane = tid & 31;
    const int warp = tid >> 5;
    const int wm   = warp & 3;      // 0..3
    const int wn   = warp >> 2;     // 0..1
    const int bm   = blockIdx.y * 128;
    const int bn   = blockIdx.x * 64;

    const int g  = lane >> 2;       // groupID 0..7
    const int tg = lane & 3;        // 0..3

    float acc[2][4][4];
#pragma unroll
    for (int i = 0; i < 2; i++)
#pragma unroll
        for (int j = 0; j < 4; j++)
#pragma unroll
            for (int r = 0; r < 4; r++) acc[i][j][r] = 0.f;

    const int lrow = tid >> 2;          // 0..63
    const int lcol = (tid & 3) * 4;     // 0,4,8,12
    const float* Xp = X + (size_t)(bm + lrow) * DM + lcol;
    const float* Wp = W + (size_t)(bn + lrow) * DM + lcol;

    for (int k0 = 0; k0 < DM; k0 += 16) {
        float4 x0 = *reinterpret_cast<const float4*>(Xp + k0);
        float4 x1 = *reinterpret_cast<const float4*>(Xp + (size_t)64 * DM + k0);
        float4 w0 = *reinterpret_cast<const float4*>(Wp + k0);
        __syncthreads();
        *reinterpret_cast<float4*>(&Xs[lrow][lcol])      = x0;
        *reinterpret_cast<float4*>(&Xs[lrow + 64][lcol]) = x1;
        *reinterpret_cast<float4*>(&Ws[lrow][lcol])      = w0;
        __syncthreads();

#pragma unroll
        for (int ks = 0; ks < 2; ks++) {
            const int kk = ks * 8;
            uint32_t ah[2][4], al[2][4], bh[4][2], bl[4][2];
#pragma unroll
            for (int mt = 0; mt < 2; mt++) {
                const int rb = wm * 32 + mt * 16;
                float v0 = Xs[rb + g][kk + tg];
                float v1 = Xs[rb + g + 8][kk + tg];
                float v2 = Xs[rb + g][kk + tg + 4];
                float v3 = Xs[rb + g + 8][kk + tg + 4];
                if (PRECISE) {
                    split_tf32(v0, ah[mt][0], al[mt][0]);
                    split_tf32(v1, ah[mt][1], al[mt][1]);
                    split_tf32(v2, ah[mt][2], al[mt][2]);
                    split_tf32(v3, ah[mt][3], al[mt][3]);
                } else {
                    ah[mt][0] = __float_as_uint(to_tf32(v0));
                    ah[mt][1] = __float_as_uint(to_tf32(v1));
                    ah[mt][2] = __float_as_uint(to_tf32(v2));
                    ah[mt][3] = __float_as_uint(to_tf32(v3));
                }
            }
#pragma unroll
            for (int nt = 0; nt < 4; nt++) {
                const int nb = wn * 32 + nt * 8;
                float v0 = Ws[nb + g][kk + tg];
                float v1 = Ws[nb + g][kk + tg + 4];
                if (PRECISE) {
                    split_tf32(v0, bh[nt][0], bl[nt][0]);
                    split_tf32(v1, bh[nt][1], bl[nt][1]);
                } else {
                    bh[nt][0] = __float_as_uint(to_tf32(v0));
                    bh[nt][1] = __float_as_uint(to_tf32(v1));
                }
            }
#pragma unroll
            for (int mt = 0; mt < 2; mt++)
#pragma unroll
                for (int nt = 0; nt < 4; nt++) {
                    mma8(acc[mt][nt], ah[mt][0], ah[mt][1], ah[mt][2], ah[mt][3],
                         bh[nt][0], bh[nt][1]);
                    if (PRECISE) {
                        mma8(acc[mt][nt], ah[mt][0], ah[mt][1], ah[mt][2], ah[mt][3],
                             bl[nt][0], bl[nt][1]);
                        mma8(acc[mt][nt], al[mt][0], al[mt][1], al[mt][2], al[mt][3],
                             bh[nt][0], bh[nt][1]);
                    }
                }
        }
    }

    // Epilogue: add bias, scatter into head-split layout [b, h, s, d]
#pragma unroll
    for (int mt = 0; mt < 2; mt++) {
#pragma unroll
        for (int nt = 0; nt < 4; nt++) {
            const int n  = bn + wn * 32 + nt * 8 + 2 * tg;
            const int h  = n / DH;
            const int d  = n % DH;
            const float b0 = bias[n];
            const float b1 = bias[n + 1];
#pragma unroll
            for (int rr = 0; rr < 2; rr++) {
                const int m = bm + wm * 32 + mt * 16 + g + rr * 8;
                const int bb = m / SEQ;
                const int s  = m % SEQ;
                float2 v;
                v.x = acc[mt][nt][rr * 2 + 0] + b0;
                v.y = acc[mt][nt][rr * 2 + 1] + b1;
                *reinterpret_cast<float2*>(
                    Out + (((size_t)(bb * NH + h)) * SEQ + s) * DH + d) = v;
            }
        }
    }
}

// ---------------------------------------------------------------------------
// Flash attention via tf32 mma. 64 q rows/block, 4 warps (16 rows each),
// key tiles of 32. Scores use 3xTF32 emulation; PV single tf32.
// ---------------------------------------------------------------------------
__global__ __launch_bounds__(128) void flash_mma_kernel(
    const float* __restrict__ Qh,
    const float* __restrict__ Kh,
    const float* __restrict__ Vh,
    float* __restrict__ out)
{
    __shared__ float Qs[64][68];       // 17408 B
    __shared__ float Ks[32][68];       //  8704 B
    __shared__ float Vs[32][72];       //  9216 B
    __shared__ float Ps[4][16][36];    //  9216 B  (per-warp P tile)

    const int tid  = threadIdx.x;
    const int lane = tid & 31;
    const int warp = tid >> 5;
    const int g    = lane >> 2;
    const int tg   = lane & 3;

    const int b  = blockIdx.z;
    const int h  = blockIdx.y;
    const int q0 = blockIdx.x * 64;
    const size_t base = ((size_t)(b * NH + h)) * SEQ * DH;

    // Stage Q block 64x64 into Qs
    {
        const int row = tid >> 1;
        const int c0  = (tid & 1) * 32;
        const float4* src = reinterpret_cast<const float4*>(Qh + base + (size_t)(q0 + row) * DH);
#pragma unroll
        for (int i = 0; i < 8; i++) {
            *reinterpret_cast<float4*>(&Qs[row][c0 + i * 4]) = src[(c0 >> 2) + i];
        }
    }
    __syncthreads();

    float oacc[8][4];
#pragma unroll
    for (int dt = 0; dt < 8; dt++)
#pragma unroll
        for (int r = 0; r < 4; r++) oacc[dt][r] = 0.f;
    float mrow0 = -1e30f, mrow1 = -1e30f;
    float lrow0 = 0.f,    lrow1 = 0.f;

    const int lr = tid >> 2;            // 0..31 (tile row)
    const int lc = (tid & 3) * 16;      // col base

    for (int kt = 0; kt < SEQ / 32; kt++) {
        // Load K,V tiles (32x64)
        const float* kp = Kh + base + (size_t)(kt * 32 + lr) * DH + lc;
        const float* vp = Vh + base + (size_t)(kt * 32 + lr) * DH + lc;
        float4 kv[4], vv[4];
#pragma unroll
        for (int i = 0; i < 4; i++) {
            kv[i] = *reinterpret_cast<const float4*>(kp + i * 4);
            vv[i] = *reinterpret_cast<const float4*>(vp + i * 4);
        }
        __syncthreads();   // previous iter readers done
#pragma unroll
        for (int i = 0; i < 4; i++) {
            *reinterpret_cast<float4*>(&Ks[lr][lc + i * 4]) = kv[i];
            *reinterpret_cast<float4*>(&Vs[lr][lc + i * 4]) = vv[i];
        }
        __syncthreads();

        // Scores: S (16 x 32) per warp, 3xTF32
        float sacc[4][4];
#pragma unroll
        for (int nt = 0; nt < 4; nt++)
#pragma unroll
            for (int r = 0; r < 4; r++) sacc[nt][r] = 0.f;

#pragma unroll
        for (int kk8 = 0; kk8 < 8; kk8++) {
            const int kc = kk8 * 8;
            uint32_t ah[4], al[4];
            split_tf32(Qs[warp * 16 + g][kc + tg],          ah[0], al[0]);
            split_tf32(Qs[warp * 16 + g + 8][kc + tg],      ah[1], al[1]);
            split_tf32(Qs[warp * 16 + g][kc + tg + 4],      ah[2], al[2]);
            split_tf32(Qs[warp * 16 + g + 8][kc + tg + 4],  ah[3], al[3]);
#pragma unroll
            for (int nt = 0; nt < 4; nt++) {
                uint32_t bh0, bl0, bh1, bl1;
                split_tf32(Ks[nt * 8 + g][kc + tg],     bh0, bl0);
                split_tf32(Ks[nt * 8 + g][kc + tg + 4], bh1, bl1);
                mma8(sacc[nt], ah[0], ah[1], ah[2], ah[3], bh0, bh1);
                mma8(sacc[nt], ah[0], ah[1], ah[2], ah[3], bl0, bl1);
                mma8(sacc[nt], al[0], al[1], al[2], al[3], bh0, bh1);
            }
        }

        // Online softmax (rows g and g+8 of this warp's 16-row strip)
        float tmax0 = sacc[0][0], tmax1 = sacc[0][2];
#pragma unroll
        for (int nt = 0; nt < 4; nt++) {
            tmax0 = fmaxf(tmax0, fmaxf(sacc[nt][0], sacc[nt][1]));
            tmax1 = fmaxf(tmax1, fmaxf(sacc[nt][2], sacc[nt][3]));
        }
        tmax0 = fmaxf(tmax0, __shfl_xor_sync(0xffffffff, tmax0, 1));
        tmax0 = fmaxf(tmax0, __shfl_xor_sync(0xffffffff, tmax0, 2));
        tmax1 = fmaxf(tmax1, __shfl_xor_sync(0xffffffff, tmax1, 1));
        tmax1 = fmaxf(tmax1, __shfl_xor_sync(0xffffffff, tmax1, 2));

        const float mnew0 = fmaxf(mrow0, tmax0);
        const float mnew1 = fmaxf(mrow1, tmax1);
        const float corr0 = __expf(mrow0 - mnew0);
        const float corr1 = __expf(mrow1 - mnew1);
        mrow0 = mnew0; mrow1 = mnew1;

        float ps0 = 0.f, ps1 = 0.f;
#pragma unroll
        for (int nt = 0; nt < 4; nt++) {
            sacc[nt][0] = __expf(sacc[nt][0] - mnew0);
            sacc[nt][1] = __expf(sacc[nt][1] - mnew0);
            sacc[nt][2] = __expf(sacc[nt][2] - mnew1);
            sacc[nt][3] = __expf(sacc[nt][3] - mnew1);
            ps0 += sacc[nt][0] + sacc[nt][1];
            ps1 += sacc[nt][2] + sacc[nt][3];
        }
        ps0 += __shfl_xor_sync(0xffffffff, ps0, 1);
        ps0 += __shfl_xor_sync(0xffffffff, ps0, 2);
        ps1 += __shfl_xor_sync(0xffffffff, ps1, 1);
        ps1 += __shfl_xor_sync(0xffffffff, ps1, 2);
        lrow0 = lrow0 * corr0 + ps0;
        lrow1 = lrow1 * corr1 + ps1;

#pragma unroll
        for (int dt = 0; dt < 8; dt++) {
            oacc[dt][0] *= corr0;
            oacc[dt][1] *= corr0;
            oacc[dt][2] *= corr1;
            oacc[dt][3] *= corr1;
        }

        // Write P tile to per-warp smem (tf32-rounded, single-pass PV)
#pragma unroll
        for (int nt = 0; nt < 4; nt++) {
            const int col = nt * 8 + 2 * tg;
            Ps[warp][g][col]         = to_tf32(sacc[nt][0]);
            Ps[warp][g][col + 1]     = to_tf32(sacc[nt][1]);
            Ps[warp][g + 8][col]     = to_tf32(sacc[nt][2]);
            Ps[warp][g + 8][col + 1] = to_tf32(sacc[nt][3]);
        }
        __syncwarp();

        // PV: O(16x64) += P(16x32) @ V(32x64)
#pragma unroll
        for (int kk = 0; kk < 4; kk++) {
            const int kc = kk * 8;
            uint32_t a0 = __float_as_uint(Ps[warp][g][kc + tg]);
            uint32_t a1 = __float_as_uint(Ps[warp][g + 8][kc + tg]);
            uint32_t a2 = __float_as_uint(Ps[warp][g][kc + tg + 4]);
            uint32_t a3 = __float_as_uint(Ps[warp][g + 8][kc + tg + 4]);
#pragma unroll
            for (int dt = 0; dt < 8; dt++) {
                uint32_t b0 = __float_as_uint(to_tf32(Vs[kc + tg][dt * 8 + g]));
                uint32_t b1 = __float_as_uint(to_tf32(Vs[kc + tg + 4][dt * 8 + g]));
                mma8(oacc[dt], a0, a1, a2, a3, b0, b1);
            }
        }
    }

    // Epilogue: normalize + write merged-head output [b, s, h*64 + d]
    const float inv0 = 1.f / lrow0;
    const float inv1 = 1.f / lrow1;
    const int row0 = q0 + warp * 16 + g;
    const int row1 = row0 + 8;
    float* o0 = out + ((size_t)(b * SEQ + row0)) * DM + h * DH;
    float* o1 = out + ((size_t)(b * SEQ + row1)) * DM + h * DH;
#pragma unroll
    for (int dt = 0; dt < 8; dt++) {
        const int col = dt * 8 + 2 * tg;
        float2 v0, v1;
        v0.x = oacc[dt][0] * inv0; v0.y = oacc[dt][1] * inv0;
        v1.x = oacc[dt][2] * inv1; v1.y = oacc[dt][3] * inv1;
        *reinterpret_cast<float2*>(o0 + col) = v0;
        *reinterpret_cast<float2*>(o1 + col) = v1;
    }
}

// ---------------------------------------------------------------------------
// Launch
// ---------------------------------------------------------------------------
extern "C" void kernel_launch(void* const* d_in, const int* in_sizes, int n_in,
                              void* d_out, int out_size)
{
    const float* q  = (const float*)d_in[0];
    const float* k  = (const float*)d_in[1];
    const float* v  = (const float*)d_in[2];
    const float* Wq = (const float*)d_in[3];
    const float* bq = (const float*)d_in[4];
    const float* Wk = (const float*)d_in[5];
    const float* bk = (const float*)d_in[6];
    const float* Wv = (const float*)d_in[7];
    const float* bv = (const float*)d_in[8];
    float* out = (float*)d_out;

    float *dq, *dk, *dv;
    cudaGetSymbolAddress((void**)&dq, g_wq);
    cudaGetSymbolAddress((void**)&dk, g_wk);
    cudaGetSymbolAddress((void**)&dv, g_wv);

    dim3 pgrid(DM / 64, M_TOTAL / 128);        // (12, 64)
    proj_mma_kernel<true ><<<pgrid, 256>>>(q, Wq, bq, dq);
    proj_mma_kernel<true ><<<pgrid, 256>>>(k, Wk, bk, dk);
    proj_mma_kernel<false><<<pgrid, 256>>>(v, Wv, bv, dv);

    dim3 agrid(SEQ / 64, NH, BATCH);           // (32, 12, 4)
    flash_mma_kernel<<<agrid, 128>>>(dq, dk, dv, out);
}

// round 6
// speedup vs baseline: 2.3908x; 1.0726x over previous
#include <cuda_runtime.h>
#include <cstdint>

#define SEQ   2048
#define DM    768
#define NH    12
#define DH    64
#define BATCH 4
#define M_TOTAL (BATCH * SEQ)   // 8192

// Head-split projection scratch: [b, h, s, d] fp32
__device__ float g_wq[BATCH * NH * SEQ * DH];
__device__ float g_wk[BATCH * NH * SEQ * DH];
__device__ float g_wv[BATCH * NH * SEQ * DH];

// ---------------------------------------------------------------------------
// tf32 helpers. HMMA.TF32 ignores the low 13 mantissa bits of each operand
// register, so round-to-nearest tf32 = add half-ulp (0x1000) to the raw bits
// and let the HW truncate. One IADD per value (vs cvt.rna = slow F2FP pipe).
//   rn_bits(x):  RN-rounded operand for single-pass mma (P, V)
//   rn_split(x): hi = RN(x) (low bits zeroed, exact for FSUB), lo = x - hi
// ---------------------------------------------------------------------------
__device__ __forceinline__ uint32_t rn_bits(float x) {
    return __float_as_uint(x) + 0x1000u;        // HW truncation completes RN
}
__device__ __forceinline__ float rn_hi(float x) {
    return __uint_as_float((__float_as_uint(x) + 0x1000u) & 0xFFFFE000u);
}
__device__ __forceinline__ void rn_split(float x, uint32_t& hi, uint32_t& lo) {
    float h = rn_hi(x);
    hi = __float_as_uint(h);
    lo = __float_as_uint(x - h);   // |lo| <= 2^-12 |x|; fed raw (trunc err ~2^-23)
}

// m16n8k8 tf32 mma, C += A*B
__device__ __forceinline__ void mma8(float* c,
                                     uint32_t a0, uint32_t a1, uint32_t a2, uint32_t a3,
                                     uint32_t b0, uint32_t b1) {
    asm volatile(
        "mma.sync.aligned.m16n8k8.row.col.f32.tf32.tf32.f32 "
        "{%0,%1,%2,%3}, {%4,%5,%6,%7}, {%8,%9}, {%0,%1,%2,%3};\n"
        : "+f"(c[0]), "+f"(c[1]), "+f"(c[2]), "+f"(c[3])
        : "r"(a0), "r"(a1), "r"(a2), "r"(a3), "r"(b0), "r"(b1));
}

// ---------------------------------------------------------------------------
// Fused projection GEMM: z in {0,1,2} selects (Q,K,V).
// Out[b,h,s,d] = X[m,:] . W[n,:] + bias[n]
// BM=128, BN=64, BK=16. 256 threads = 8 warps (4m x 2n), warp tile 32x32.
// Q/K use 3xTF32 (RN hi/lo), V single-pass RN tf32.
// ---------------------------------------------------------------------------
__global__ __launch_bounds__(256) void proj_fused_kernel(
    const float* __restrict__ Xq, const float* __restrict__ Xk, const float* __restrict__ Xv,
    const float* __restrict__ Wq, const float* __restrict__ bq,
    const float* __restrict__ Wk, const float* __restrict__ bk,
    const float* __restrict__ Wv, const float* __restrict__ bv,
    float* __restrict__ Oq, float* __restrict__ Ok, float* __restrict__ Ov)
{
    const int z = blockIdx.z;
    const float* X    = (z == 0) ? Xq : (z == 1) ? Xk : Xv;
    const float* W    = (z == 0) ? Wq : (z == 1) ? Wk : Wv;
    const float* bias = (z == 0) ? bq : (z == 1) ? bk : bv;
    float* Out        = (z == 0) ? Oq : (z == 1) ? Ok : Ov;
    const bool PRECISE = (z != 2);

    __shared__ float Xs[128][20];
    __shared__ float Ws[64][20];

    const int tid  = threadIdx.x;
    const int lane = tid & 31;
    const int warp = tid >> 5;
    const int wm   = warp & 3;
    const int wn   = warp >> 2;
    const int bm   = blockIdx.y * 128;
    const int bn   = blockIdx.x * 64;

    const int g  = lane >> 2;
    const int tg = lane & 3;

    float acc[2][4][4];
#pragma unroll
    for (int i = 0; i < 2; i++)
#pragma unroll
        for (int j = 0; j < 4; j++)
#pragma unroll
            for (int r = 0; r < 4; r++) acc[i][j][r] = 0.f;

    const int lrow = tid >> 2;
    const int lcol = (tid & 3) * 4;
    const float* Xp = X + (size_t)(bm + lrow) * DM + lcol;
    const float* Wp = W + (size_t)(bn + lrow) * DM + lcol;

    for (int k0 = 0; k0 < DM; k0 += 16) {
        float4 x0 = *reinterpret_cast<const float4*>(Xp + k0);
        float4 x1 = *reinterpret_cast<const float4*>(Xp + (size_t)64 * DM + k0);
        float4 w0 = *reinterpret_cast<const float4*>(Wp + k0);
        __syncthreads();
        *reinterpret_cast<float4*>(&Xs[lrow][lcol])      = x0;
        *reinterpret_cast<float4*>(&Xs[lrow + 64][lcol]) = x1;
        *reinterpret_cast<float4*>(&Ws[lrow][lcol])      = w0;
        __syncthreads();

#pragma unroll
        for (int ks = 0; ks < 2; ks++) {
            const int kk = ks * 8;
            uint32_t ah[2][4], al[2][4], bh[4][2], bl[4][2];
#pragma unroll
            for (int mt = 0; mt < 2; mt++) {
                const int rb = wm * 32 + mt * 16;
                float v0 = Xs[rb + g][kk + tg];
                float v1 = Xs[rb + g + 8][kk + tg];
                float v2 = Xs[rb + g][kk + tg + 4];
                float v3 = Xs[rb + g + 8][kk + tg + 4];
                if (PRECISE) {
                    rn_split(v0, ah[mt][0], al[mt][0]);
                    rn_split(v1, ah[mt][1], al[mt][1]);
                    rn_split(v2, ah[mt][2], al[mt][2]);
                    rn_split(v3, ah[mt][3], al[mt][3]);
                } else {
                    ah[mt][0] = rn_bits(v0);
                    ah[mt][1] = rn_bits(v1);
                    ah[mt][2] = rn_bits(v2);
                    ah[mt][3] = rn_bits(v3);
                }
            }
#pragma unroll
            for (int nt = 0; nt < 4; nt++) {
                const int nb = wn * 32 + nt * 8;
                float v0 = Ws[nb + g][kk + tg];
                float v1 = Ws[nb + g][kk + tg + 4];
                if (PRECISE) {
                    rn_split(v0, bh[nt][0], bl[nt][0]);
                    rn_split(v1, bh[nt][1], bl[nt][1]);
                } else {
                    bh[nt][0] = rn_bits(v0);
                    bh[nt][1] = rn_bits(v1);
                }
            }
#pragma unroll
            for (int mt = 0; mt < 2; mt++)
#pragma unroll
                for (int nt = 0; nt < 4; nt++) {
                    mma8(acc[mt][nt], ah[mt][0], ah[mt][1], ah[mt][2], ah[mt][3],
                         bh[nt][0], bh[nt][1]);
                    if (PRECISE) {
                        mma8(acc[mt][nt], ah[mt][0], ah[mt][1], ah[mt][2], ah[mt][3],
                             bl[nt][0], bl[nt][1]);
                        mma8(acc[mt][nt], al[mt][0], al[mt][1], al[mt][2], al[mt][3],
                             bh[nt][0], bh[nt][1]);
                    }
                }
        }
    }

    // Epilogue: add bias, scatter into head-split layout [b, h, s, d]
#pragma unroll
    for (int mt = 0; mt < 2; mt++) {
#pragma unroll
        for (int nt = 0; nt < 4; nt++) {
            const int n  = bn + wn * 32 + nt * 8 + 2 * tg;
            const int h  = n / DH;
            const int d  = n % DH;
            const float b0 = bias[n];
            const float b1 = bias[n + 1];
#pragma unroll
            for (int rr = 0; rr < 2; rr++) {
                const int m = bm + wm * 32 + mt * 16 + g + rr * 8;
                const int bb = m / SEQ;
                const int s  = m % SEQ;
                float2 v;
                v.x = acc[mt][nt][rr * 2 + 0] + b0;
                v.y = acc[mt][nt][rr * 2 + 1] + b1;
                *reinterpret_cast<float2*>(
                    Out + (((size_t)(bb * NH + h)) * SEQ + s) * DH + d) = v;
            }
        }
    }
}

// ---------------------------------------------------------------------------
// Flash attention via tf32 mma. 64 q rows/block, 4 warps (16 rows each),
// key tiles of 32. Q hi/lo fragments hoisted into registers (loop-invariant);
// K RN-split cooperatively at stage time; V pre-rounded at stage; P rounded
// with one IADD at store. All rounding unbiased.
// ---------------------------------------------------------------------------
__global__ __launch_bounds__(128, 3) void flash_mma_kernel(
    const float* __restrict__ Qh,
    const float* __restrict__ Kh,
    const float* __restrict__ Vh,
    float* __restrict__ out)
{
    __shared__ float Ks [32][68];      // K hi (RN, low bits zero)
    __shared__ float Ksl[32][68];      // K lo
    __shared__ float Vs [32][72];      // V pre-rounded bits (RN after HW trunc)
    __shared__ float Ps [4][16][36];   // per-warp P tile (pre-rounded bits)

    const int tid  = threadIdx.x;
    const int lane = tid & 31;
    const int warp = tid >> 5;
    const int g    = lane >> 2;
    const int tg   = lane & 3;

    const int b  = blockIdx.z;
    const int h  = blockIdx.y;
    const int q0 = blockIdx.x * 64;
    const size_t base = ((size_t)(b * NH + h)) * SEQ * DH;

    // Hoisted Q fragments: rows (q0+warp*16+g, +8), cols kc+tg / kc+tg+4
    uint32_t qh[8][4], ql[8][4];
    {
        const float* q0p = Qh + base + (size_t)(q0 + warp * 16 + g) * DH;
        const float* q1p = q0p + 8 * DH;
#pragma unroll
        for (int kk8 = 0; kk8 < 8; kk8++) {
            const int kc = kk8 * 8;
            rn_split(__ldg(q0p + kc + tg),     qh[kk8][0], ql[kk8][0]);
            rn_split(__ldg(q1p + kc + tg),     qh[kk8][1], ql[kk8][1]);
            rn_split(__ldg(q0p + kc + tg + 4), qh[kk8][2], ql[kk8][2]);
            rn_split(__ldg(q1p + kc + tg + 4), qh[kk8][3], ql[kk8][3]);
        }
    }

    float oacc[8][4];
#pragma unroll
    for (int dt = 0; dt < 8; dt++)
#pragma unroll
        for (int r = 0; r < 4; r++) oacc[dt][r] = 0.f;
    float mrow0 = -1e30f, mrow1 = -1e30f;
    float lrow0 = 0.f,    lrow1 = 0.f;

    const int lr = tid >> 2;            // 0..31 (tile row)
    const int lc = (tid & 3) * 16;      // col base

    for (int kt = 0; kt < SEQ / 32; kt++) {
        // Load K,V tiles (32x64); RN-split K, pre-round V
        const float* kp = Kh + base + (size_t)(kt * 32 + lr) * DH + lc;
        const float* vp = Vh + base + (size_t)(kt * 32 + lr) * DH + lc;
        float4 kv[4], vv[4];
#pragma unroll
        for (int i = 0; i < 4; i++) {
            kv[i] = *reinterpret_cast<const float4*>(kp + i * 4);
            vv[i] = *reinterpret_cast<const float4*>(vp + i * 4);
        }
        __syncthreads();   // previous iter readers done
#pragma unroll
        for (int i = 0; i < 4; i++) {
            float4 hi, lo, vr;
            hi.x = rn_hi(kv[i].x);  lo.x = kv[i].x - hi.x;
            hi.y = rn_hi(kv[i].y);  lo.y = kv[i].y - hi.y;
            hi.z = rn_hi(kv[i].z);  lo.z = kv[i].z - hi.z;
            hi.w = rn_hi(kv[i].w);  lo.w = kv[i].w - hi.w;
            vr.x = __uint_as_float(rn_bits(vv[i].x));
            vr.y = __uint_as_float(rn_bits(vv[i].y));
            vr.z = __uint_as_float(rn_bits(vv[i].z));
            vr.w = __uint_as_float(rn_bits(vv[i].w));
            *reinterpret_cast<float4*>(&Ks [lr][lc + i * 4]) = hi;
            *reinterpret_cast<float4*>(&Ksl[lr][lc + i * 4]) = lo;
            *reinterpret_cast<float4*>(&Vs [lr][lc + i * 4]) = vr;
        }
        __syncthreads();

        // Scores: S (16 x 32) per warp, 3xTF32
        float sacc[4][4];
#pragma unroll
        for (int nt = 0; nt < 4; nt++)
#pragma unroll
            for (int r = 0; r < 4; r++) sacc[nt][r] = 0.f;

#pragma unroll
        for (int kk8 = 0; kk8 < 8; kk8++) {
            const int kc = kk8 * 8;
#pragma unroll
            for (int nt = 0; nt < 4; nt++) {
                uint32_t bh0 = __float_as_uint(Ks [nt * 8 + g][kc + tg]);
                uint32_t bh1 = __float_as_uint(Ks [nt * 8 + g][kc + tg + 4]);
                uint32_t bl0 = __float_as_uint(Ksl[nt * 8 + g][kc + tg]);
                uint32_t bl1 = __float_as_uint(Ksl[nt * 8 + g][kc + tg + 4]);
                mma8(sacc[nt], qh[kk8][0], qh[kk8][1], qh[kk8][2], qh[kk8][3], bh0, bh1);
                mma8(sacc[nt], qh[kk8][0], qh[kk8][1], qh[kk8][2], qh[kk8][3], bl0, bl1);
                mma8(sacc[nt], ql[kk8][0], ql[kk8][1], ql[kk8][2], ql[kk8][3], bh0, bh1);
            }
        }

        // Online softmax (rows g and g+8 of this warp's 16-row strip)
        float tmax0 = sacc[0][0], tmax1 = sacc[0][2];
#pragma unroll
        for (int nt = 0; nt < 4; nt++) {
            tmax0 = fmaxf(tmax0, fmaxf(sacc[nt][0], sacc[nt][1]));
            tmax1 = fmaxf(tmax1, fmaxf(sacc[nt][2], sacc[nt][3]));
        }
        tmax0 = fmaxf(tmax0, __shfl_xor_sync(0xffffffff, tmax0, 1));
        tmax0 = fmaxf(tmax0, __shfl_xor_sync(0xffffffff, tmax0, 2));
        tmax1 = fmaxf(tmax1, __shfl_xor_sync(0xffffffff, tmax1, 1));
        tmax1 = fmaxf(tmax1, __shfl_xor_sync(0xffffffff, tmax1, 2));

        const float mnew0 = fmaxf(mrow0, tmax0);
        const float mnew1 = fmaxf(mrow1, tmax1);
        const float corr0 = __expf(mrow0 - mnew0);
        const float corr1 = __expf(mrow1 - mnew1);
        mrow0 = mnew0; mrow1 = mnew1;

        float ps0 = 0.f, ps1 = 0.f;
#pragma unroll
        for (int nt = 0; nt < 4; nt++) {
            sacc[nt][0] = __expf(sacc[nt][0] - mnew0);
            sacc[nt][1] = __expf(sacc[nt][1] - mnew0);
            sacc[nt][2] = __expf(sacc[nt][2] - mnew1);
            sacc[nt][3] = __expf(sacc[nt][3] - mnew1);
            ps0 += sacc[nt][0] + sacc[nt][1];
            ps1 += sacc[nt][2] + sacc[nt][3];
        }
        ps0 += __shfl_xor_sync(0xffffffff, ps0, 1);
        ps0 += __shfl_xor_sync(0xffffffff, ps0, 2);
        ps1 += __shfl_xor_sync(0xffffffff, ps1, 1);
        ps1 += __shfl_xor_sync(0xffffffff, ps1, 2);
        lrow0 = lrow0 * corr0 + ps0;
        lrow1 = lrow1 * corr1 + ps1;

#pragma unroll
        for (int dt = 0; dt < 8; dt++) {
            oacc[dt][0] *= corr0;
            oacc[dt][1] *= corr0;
            oacc[dt][2] *= corr1;
            oacc[dt][3] *= corr1;
        }

        // P tile to per-warp smem, pre-rounded (RN after HW trunc)
#pragma unroll
        for (int nt = 0; nt < 4; nt++) {
            const int col = nt * 8 + 2 * tg;
            *reinterpret_cast<uint2*>(&Ps[warp][g][col]) =
                make_uint2(rn_bits(sacc[nt][0]), rn_bits(sacc[nt][1]));
            *reinterpret_cast<uint2*>(&Ps[warp][g + 8][col]) =
                make_uint2(rn_bits(sacc[nt][2]), rn_bits(sacc[nt][3]));
        }
        __syncwarp();

        // PV: O(16x64) += P(16x32) @ V(32x64), single-pass RN tf32
#pragma unroll
        for (int kk = 0; kk < 4; kk++) {
            const int kc = kk * 8;
            uint32_t a0 = __float_as_uint(Ps[warp][g][kc + tg]);
            uint32_t a1 = __float_as_uint(Ps[warp][g + 8][kc + tg]);
            uint32_t a2 = __float_as_uint(Ps[warp][g][kc + tg + 4]);
            uint32_t a3 = __float_as_uint(Ps[warp][g + 8][kc + tg + 4]);
#pragma unroll
            for (int dt = 0; dt < 8; dt++) {
                uint32_t b0 = __float_as_uint(Vs[kc + tg][dt * 8 + g]);
                uint32_t b1 = __float_as_uint(Vs[kc + tg + 4][dt * 8 + g]);
                mma8(oacc[dt], a0, a1, a2, a3, b0, b1);
            }
        }
    }

    // Epilogue: normalize + write merged-head output [b, s, h*64 + d]
    const float inv0 = 1.f / lrow0;
    const float inv1 = 1.f / lrow1;
    const int row0 = q0 + warp * 16 + g;
    const int row1 = row0 + 8;
    float* o0 = out + ((size_t)(b * SEQ + row0)) * DM + h * DH;
    float* o1 = out + ((size_t)(b * SEQ + row1)) * DM + h * DH;
#pragma unroll
    for (int dt = 0; dt < 8; dt++) {
        const int col = dt * 8 + 2 * tg;
        float2 v0, v1;
        v0.x = oacc[dt][0] * inv0; v0.y = oacc[dt][1] * inv0;
        v1.x = oacc[dt][2] * inv1; v1.y = oacc[dt][3] * inv1;
        *reinterpret_cast<float2*>(o0 + col) = v0;
        *reinterpret_cast<float2*>(o1 + col) = v1;
    }
}

// ---------------------------------------------------------------------------
// Launch
// ---------------------------------------------------------------------------
extern "C" void kernel_launch(void* const* d_in, const int* in_sizes, int n_in,
                              void* d_out, int out_size)
{
    const float* q  = (const float*)d_in[0];
    const float* k  = (const float*)d_in[1];
    const float* v  = (const float*)d_in[2];
    const float* Wq = (const float*)d_in[3];
    const float* bq = (const float*)d_in[4];
    const float* Wk = (const float*)d_in[5];
    const float* bk = (const float*)d_in[6];
    const float* Wv = (const float*)d_in[7];
    const float* bv = (const float*)d_in[8];
    float* out = (float*)d_out;

    float *dq, *dk, *dv;
    cudaGetSymbolAddress((void**)&dq, g_wq);
    cudaGetSymbolAddress((void**)&dk, g_wk);
    cudaGetSymbolAddress((void**)&dv, g_wv);

    dim3 pgrid(DM / 64, M_TOTAL / 128, 3);     // (12, 64, 3)
    proj_fused_kernel<<<pgrid, 256>>>(q, k, v, Wq, bq, Wk, bk, Wv, bv, dq, dk, dv);

    dim3 agrid(SEQ / 64, NH, BATCH);           // (32, 12, 4)
    flash_mma_kernel<<<agrid, 128>>>(dq, dk, dv, out);
}

// round 7
// speedup vs baseline: 2.9604x; 1.2382x over previous
#include <cuda_runtime.h>
#include <cstdint>

#define SEQ   2048
#define DM    768
#define NH    12
#define DH    64
#define BATCH 4
#define M_TOTAL (BATCH * SEQ)   // 8192

// Head-split projection scratch: [b, h, s, d] fp32
__device__ float g_wq[BATCH * NH * SEQ * DH];
__device__ float g_wk[BATCH * NH * SEQ * DH];
__device__ float g_wv[BATCH * NH * SEQ * DH];

// ---------------------------------------------------------------------------
// tf32 helpers. HMMA.TF32 ignores the low 13 mantissa bits of each operand.
//  - Single-pass operands (P, V, V-proj) need unbiased rounding: RN via +0x1000.
//  - Split-path operands use TRUNC split: hi = trunc13(x) (fed as raw bits),
//    lo = x - hi (exact). hi+lo == x exactly, so no bias; only the tiny
//    al*bl term (~2^-22) is dropped.
// ---------------------------------------------------------------------------
__device__ __forceinline__ uint32_t rn_bits(float x) {
    return __float_as_uint(x) + 0x1000u;        // HW truncation completes RN
}
__device__ __forceinline__ void tr_split(float x, uint32_t& hi, uint32_t& lo) {
    uint32_t b = __float_as_uint(x);
    hi = b;                                      // HW uses trunc13(x)
    lo = __float_as_uint(x - __uint_as_float(b & 0xFFFFE000u));
}

// m16n8k8 tf32 mma, C += A*B
__device__ __forceinline__ void mma8(float* c,
                                     uint32_t a0, uint32_t a1, uint32_t a2, uint32_t a3,
                                     uint32_t b0, uint32_t b1) {
    asm volatile(
        "mma.sync.aligned.m16n8k8.row.col.f32.tf32.tf32.f32 "
        "{%0,%1,%2,%3}, {%4,%5,%6,%7}, {%8,%9}, {%0,%1,%2,%3};\n"
        : "+f"(c[0]), "+f"(c[1]), "+f"(c[2]), "+f"(c[3])
        : "r"(a0), "r"(a1), "r"(a2), "r"(a3), "r"(b0), "r"(b1));
}

// cp.async 16B, L1-bypass
__device__ __forceinline__ void cp16(uint32_t smem_addr, const void* gptr) {
    asm volatile("cp.async.cg.shared.global [%0], [%1], 16;\n"
                 :: "r"(smem_addr), "l"(gptr));
}
__device__ __forceinline__ void cp_commit() {
    asm volatile("cp.async.commit_group;\n");
}

// ---------------------------------------------------------------------------
// Fused projection GEMM: z in {0,1,2} selects (Q,K,V).
// Out[b,h,s,d] = X[m,:] . W[n,:] + bias[n]
// BM=128, BN=64, BK=16. 256 threads = 8 warps (4m x 2n), warp tile 32x32.
// Q/K: 3xTF32 trunc-split. V: single-pass RN tf32.
// Double-buffered cp.async staging of X and W tiles.
// ---------------------------------------------------------------------------
__global__ __launch_bounds__(256) void proj_fused_kernel(
    const float* __restrict__ Xq, const float* __restrict__ Xk, const float* __restrict__ Xv,
    const float* __restrict__ Wq, const float* __restrict__ bq,
    const float* __restrict__ Wk, const float* __restrict__ bk,
    const float* __restrict__ Wv, const float* __restrict__ bv,
    float* __restrict__ Oq, float* __restrict__ Ok, float* __restrict__ Ov)
{
    const int z = blockIdx.z;
    const float* X    = (z == 0) ? Xq : (z == 1) ? Xk : Xv;
    const float* W    = (z == 0) ? Wq : (z == 1) ? Wk : Wv;
    const float* bias = (z == 0) ? bq : (z == 1) ? bk : bv;
    float* Out        = (z == 0) ? Oq : (z == 1) ? Ok : Ov;
    const bool PRECISE = (z != 2);

    __shared__ float Xs[2][128][20];
    __shared__ float Ws[2][64][20];

    const int tid  = threadIdx.x;
    const int lane = tid & 31;
    const int warp = tid >> 5;
    const int wm   = warp & 3;
    const int wn   = warp >> 2;
    const int bm   = blockIdx.y * 128;
    const int bn   = blockIdx.x * 64;

    const int g  = lane >> 2;
    const int tg = lane & 3;

    float acc[2][4][4];
#pragma unroll
    for (int i = 0; i < 2; i++)
#pragma unroll
        for (int j = 0; j < 4; j++)
#pragma unroll
            for (int r = 0; r < 4; r++) acc[i][j][r] = 0.f;

    // cp.async staging addresses
    const uint32_t xs_base = (uint32_t)__cvta_generic_to_shared(&Xs[0][0][0]);
    const uint32_t ws_base = (uint32_t)__cvta_generic_to_shared(&Ws[0][0][0]);
    const int xrow0 = tid >> 2,  xc0 = (tid & 3) * 4;            // X: 2 f4/thread
    const int wrow  = tid >> 2,  wc  = (tid & 3) * 4;            // W: 1 f4/thread

    const int NT = DM / 16;   // 48

    // issue tile kt into buffer kt&1
    auto issue = [&](int kt) {
        const int k0 = kt * 16;
        const uint32_t xb = xs_base + (uint32_t)((kt & 1) * 128 * 20 * 4);
        const uint32_t wb = ws_base + (uint32_t)((kt & 1) * 64 * 20 * 4);
        cp16(xb + (uint32_t)((xrow0      ) * 20 + xc0) * 4,
             X + (size_t)(bm + xrow0) * DM + k0 + xc0);
        cp16(xb + (uint32_t)((xrow0 + 64 ) * 20 + xc0) * 4,
             X + (size_t)(bm + xrow0 + 64) * DM + k0 + xc0);
        cp16(wb + (uint32_t)(wrow * 20 + wc) * 4,
             W + (size_t)(bn + wrow) * DM + k0 + wc);
        cp_commit();
    };

    issue(0);
    issue(1);

    for (int kt = 0; kt < NT; kt++) {
        if (kt + 1 < NT) asm volatile("cp.async.wait_group 1;\n");
        else             asm volatile("cp.async.wait_group 0;\n");
        __syncthreads();
        const int buf = kt & 1;

#pragma unroll
        for (int ks = 0; ks < 2; ks++) {
            const int kk = ks * 8;
            uint32_t ah[2][4], al[2][4], bh[4][2], bl[4][2];
#pragma unroll
            for (int mt = 0; mt < 2; mt++) {
                const int rb = wm * 32 + mt * 16;
                float v0 = Xs[buf][rb + g][kk + tg];
                float v1 = Xs[buf][rb + g + 8][kk + tg];
                float v2 = Xs[buf][rb + g][kk + tg + 4];
                float v3 = Xs[buf][rb + g + 8][kk + tg + 4];
                if (PRECISE) {
                    tr_split(v0, ah[mt][0], al[mt][0]);
                    tr_split(v1, ah[mt][1], al[mt][1]);
                    tr_split(v2, ah[mt][2], al[mt][2]);
                    tr_split(v3, ah[mt][3], al[mt][3]);
                } else {
                    ah[mt][0] = rn_bits(v0);
                    ah[mt][1] = rn_bits(v1);
                    ah[mt][2] = rn_bits(v2);
                    ah[mt][3] = rn_bits(v3);
                }
            }
#pragma unroll
            for (int nt = 0; nt < 4; nt++) {
                const int nb = wn * 32 + nt * 8;
                float v0 = Ws[buf][nb + g][kk + tg];
                float v1 = Ws[buf][nb + g][kk + tg + 4];
                if (PRECISE) {
                    tr_split(v0, bh[nt][0], bl[nt][0]);
                    tr_split(v1, bh[nt][1], bl[nt][1]);
                } else {
                    bh[nt][0] = rn_bits(v0);
                    bh[nt][1] = rn_bits(v1);
                }
            }
#pragma unroll
            for (int mt = 0; mt < 2; mt++)
#pragma unroll
                for (int nt = 0; nt < 4; nt++) {
                    mma8(acc[mt][nt], ah[mt][0], ah[mt][1], ah[mt][2], ah[mt][3],
                         bh[nt][0], bh[nt][1]);
                    if (PRECISE) {
                        mma8(acc[mt][nt], ah[mt][0], ah[mt][1], ah[mt][2], ah[mt][3],
                             bl[nt][0], bl[nt][1]);
                        mma8(acc[mt][nt], al[mt][0], al[mt][1], al[mt][2], al[mt][3],
                             bh[nt][0], bh[nt][1]);
                    }
                }
        }
        __syncthreads();
        if (kt + 2 < NT) issue(kt + 2);
    }

    // Epilogue: add bias, scatter into head-split layout [b, h, s, d]
#pragma unroll
    for (int mt = 0; mt < 2; mt++) {
#pragma unroll
        for (int nt = 0; nt < 4; nt++) {
            const int n  = bn + wn * 32 + nt * 8 + 2 * tg;
            const int h  = n / DH;
            const int d  = n % DH;
            const float b0 = bias[n];
            const float b1 = bias[n + 1];
#pragma unroll
            for (int rr = 0; rr < 2; rr++) {
                const int m = bm + wm * 32 + mt * 16 + g + rr * 8;
                const int bb = m / SEQ;
                const int s  = m % SEQ;
                float2 v;
                v.x = acc[mt][nt][rr * 2 + 0] + b0;
                v.y = acc[mt][nt][rr * 2 + 1] + b1;
                *reinterpret_cast<float2*>(
                    Out + (((size_t)(bb * NH + h)) * SEQ + s) * DH + d) = v;
            }
        }
    }
}

// ---------------------------------------------------------------------------
// Flash attention via tf32 mma. 64 q rows/block, 4 warps (16 rows each),
// key tiles of 32, double-buffered cp.async K/V staging (raw tiles).
// Q trunc-split hoisted to registers; K trunc-split in-register at consume
// (1 LDS + 2 ALU replaces 2 LDS); V RN'd with one IADD at consume;
// P pre-rounded RN at store.
// ---------------------------------------------------------------------------
__global__ __launch_bounds__(128, 3) void flash_mma_kernel(
    const float* __restrict__ Qh,
    const float* __restrict__ Kh,
    const float* __restrict__ Vh,
    float* __restrict__ out)
{
    __shared__ float Ks[2][32][68];    // raw K
    __shared__ float Vs[2][32][72];    // raw V
    __shared__ float Ps[4][16][36];    // per-warp P tile (pre-rounded bits)

    const int tid  = threadIdx.x;
    const int lane = tid & 31;
    const int warp = tid >> 5;
    const int g    = lane >> 2;
    const int tg   = lane & 3;

    const int b  = blockIdx.z;
    const int h  = blockIdx.y;
    const int q0 = blockIdx.x * 64;
    const size_t base = ((size_t)(b * NH + h)) * SEQ * DH;

    // cp.async staging: 32 rows x 64 floats per tile; 4 f4/thread each for K,V
    const uint32_t ks_base = (uint32_t)__cvta_generic_to_shared(&Ks[0][0][0]);
    const uint32_t vs_base = (uint32_t)__cvta_generic_to_shared(&Vs[0][0][0]);

    auto issue = [&](int kt) {
        const uint32_t kb = ks_base + (uint32_t)((kt & 1) * 32 * 68 * 4);
        const uint32_t vb = vs_base + (uint32_t)((kt & 1) * 32 * 72 * 4);
        const float* kp = Kh + base + (size_t)(kt * 32) * DH;
        const float* vp = Vh + base + (size_t)(kt * 32) * DH;
#pragma unroll
        for (int i = 0; i < 4; i++) {
            const int idx = i * 128 + tid;
            const int row = idx >> 4;
            const int c   = (idx & 15) * 4;
            cp16(kb + (uint32_t)(row * 68 + c) * 4, kp + row * 64 + c);
            cp16(vb + (uint32_t)(row * 72 + c) * 4, vp + row * 64 + c);
        }
        cp_commit();
    };

    // Hoisted Q fragments (trunc split): rows (q0+warp*16+g, +8)
    uint32_t qh[8][4], ql[8][4];
    {
        const float* q0p = Qh + base + (size_t)(q0 + warp * 16 + g) * DH;
        const float* q1p = q0p + 8 * DH;
#pragma unroll
        for (int kk8 = 0; kk8 < 8; kk8++) {
            const int kc = kk8 * 8;
            tr_split(__ldg(q0p + kc + tg),     qh[kk8][0], ql[kk8][0]);
            tr_split(__ldg(q1p + kc + tg),     qh[kk8][1], ql[kk8][1]);
            tr_split(__ldg(q0p + kc + tg + 4), qh[kk8][2], ql[kk8][2]);
            tr_split(__ldg(q1p + kc + tg + 4), qh[kk8][3], ql[kk8][3]);
        }
    }

    issue(0);
    issue(1);

    float oacc[8][4];
#pragma unroll
    for (int dt = 0; dt < 8; dt++)
#pragma unroll
        for (int r = 0; r < 4; r++) oacc[dt][r] = 0.f;
    float mrow0 = -1e30f, mrow1 = -1e30f;
    float lrow0 = 0.f,    lrow1 = 0.f;

    const int NT = SEQ / 32;   // 64

    for (int kt = 0; kt < NT; kt++) {
        if (kt + 1 < NT) asm volatile("cp.async.wait_group 1;\n");
        else             asm volatile("cp.async.wait_group 0;\n");
        __syncthreads();
        const int buf = kt & 1;

        // Scores: S (16 x 32) per warp, 3xTF32 with in-register K split
        float sacc[4][4];
#pragma unroll
        for (int nt = 0; nt < 4; nt++)
#pragma unroll
            for (int r = 0; r < 4; r++) sacc[nt][r] = 0.f;

#pragma unroll
        for (int kk8 = 0; kk8 < 8; kk8++) {
            const int kc = kk8 * 8;
#pragma unroll
            for (int nt = 0; nt < 4; nt++) {
                float x0 = Ks[buf][nt * 8 + g][kc + tg];
                float x1 = Ks[buf][nt * 8 + g][kc + tg + 4];
                uint32_t bh0, bl0, bh1, bl1;
                tr_split(x0, bh0, bl0);
                tr_split(x1, bh1, bl1);
                mma8(sacc[nt], qh[kk8][0], qh[kk8][1], qh[kk8][2], qh[kk8][3], bh0, bh1);
                mma8(sacc[nt], qh[kk8][0], qh[kk8][1], qh[kk8][2], qh[kk8][3], bl0, bl1);
                mma8(sacc[nt], ql[kk8][0], ql[kk8][1], ql[kk8][2], ql[kk8][3], bh0, bh1);
            }
        }

        // Online softmax (rows g and g+8 of this warp's 16-row strip)
        float tmax0 = sacc[0][0], tmax1 = sacc[0][2];
#pragma unroll
        for (int nt = 0; nt < 4; nt++) {
            tmax0 = fmaxf(tmax0, fmaxf(sacc[nt][0], sacc[nt][1]));
            tmax1 = fmaxf(tmax1, fmaxf(sacc[nt][2], sacc[nt][3]));
        }
        tmax0 = fmaxf(tmax0, __shfl_xor_sync(0xffffffff, tmax0, 1));
        tmax0 = fmaxf(tmax0, __shfl_xor_sync(0xffffffff, tmax0, 2));
        tmax1 = fmaxf(tmax1, __shfl_xor_sync(0xffffffff, tmax1, 1));
        tmax1 = fmaxf(tmax1, __shfl_xor_sync(0xffffffff, tmax1, 2));

        const float mnew0 = fmaxf(mrow0, tmax0);
        const float mnew1 = fmaxf(mrow1, tmax1);
        const float corr0 = __expf(mrow0 - mnew0);
        const float corr1 = __expf(mrow1 - mnew1);
        mrow0 = mnew0; mrow1 = mnew1;

        float ps0 = 0.f, ps1 = 0.f;
#pragma unroll
        for (int nt = 0; nt < 4; nt++) {
            sacc[nt][0] = __expf(sacc[nt][0] - mnew0);
            sacc[nt][1] = __expf(sacc[nt][1] - mnew0);
            sacc[nt][2] = __expf(sacc[nt][2] - mnew1);
            sacc[nt][3] = __expf(sacc[nt][3] - mnew1);
            ps0 += sacc[nt][0] + sacc[nt][1];
            ps1 += sacc[nt][2] + sacc[nt][3];
        }
        ps0 += __shfl_xor_sync(0xffffffff, ps0, 1);
        ps0 += __shfl_xor_sync(0xffffffff, ps0, 2);
        ps1 += __shfl_xor_sync(0xffffffff, ps1, 1);
        ps1 += __shfl_xor_sync(0xffffffff, ps1, 2);
        lrow0 = lrow0 * corr0 + ps0;
        lrow1 = lrow1 * corr1 + ps1;

#pragma unroll
        for (int dt = 0; dt < 8; dt++) {
            oacc[dt][0] *= corr0;
            oacc[dt][1] *= corr0;
            oacc[dt][2] *= corr1;
            oacc[dt][3] *= corr1;
        }

        // P tile to per-warp smem, pre-rounded (RN after HW trunc)
#pragma unroll
        for (int nt = 0; nt < 4; nt++) {
            const int col = nt * 8 + 2 * tg;
            *reinterpret_cast<uint2*>(&Ps[warp][g][col]) =
                make_uint2(rn_bits(sacc[nt][0]), rn_bits(sacc[nt][1]));
            *reinterpret_cast<uint2*>(&Ps[warp][g + 8][col]) =
                make_uint2(rn_bits(sacc[nt][2]), rn_bits(sacc[nt][3]));
        }
        __syncwarp();

        // PV: O(16x64) += P(16x32) @ V(32x64); V RN'd via IADD at consume
#pragma unroll
        for (int kk = 0; kk < 4; kk++) {
            const int kc = kk * 8;
            uint32_t a0 = __float_as_uint(Ps[warp][g][kc + tg]);
            uint32_t a1 = __float_as_uint(Ps[warp][g + 8][kc + tg]);
            uint32_t a2 = __float_as_uint(Ps[warp][g][kc + tg + 4]);
            uint32_t a3 = __float_as_uint(Ps[warp][g + 8][kc + tg + 4]);
#pragma unroll
            for (int dt = 0; dt < 8; dt++) {
                uint32_t b0 = __float_as_uint(Vs[buf][kc + tg][dt * 8 + g]) + 0x1000u;
                uint32_t b1 = __float_as_uint(Vs[buf][kc + tg + 4][dt * 8 + g]) + 0x1000u;
                mma8(oacc[dt], a0, a1, a2, a3, b0, b1);
            }
        }

        __syncthreads();
        if (kt + 2 < NT) issue(kt + 2);
    }

    // Epilogue: normalize + write merged-head output [b, s, h*64 + d]
    const float inv0 = 1.f / lrow0;
    const float inv1 = 1.f / lrow1;
    const int row0 = q0 + warp * 16 + g;
    const int row1 = row0 + 8;
    float* o0 = out + ((size_t)(b * SEQ + row0)) * DM + h * DH;
    float* o1 = out + ((size_t)(b * SEQ + row1)) * DM + h * DH;
#pragma unroll
    for (int dt = 0; dt < 8; dt++) {
        const int col = dt * 8 + 2 * tg;
        float2 v0, v1;
        v0.x = oacc[dt][0] * inv0; v0.y = oacc[dt][1] * inv0;
        v1.x = oacc[dt][2] * inv1; v1.y = oacc[dt][3] * inv1;
        *reinterpret_cast<float2*>(o0 + col) = v0;
        *reinterpret_cast<float2*>(o1 + col) = v1;
    }
}

// ---------------------------------------------------------------------------
// Launch
// ---------------------------------------------------------------------------
extern "C" void kernel_launch(void* const* d_in, const int* in_sizes, int n_in,
                              void* d_out, int out_size)
{
    const float* q  = (const float*)d_in[0];
    const float* k  = (const float*)d_in[1];
    const float* v  = (const float*)d_in[2];
    const float* Wq = (const float*)d_in[3];
    const float* bq = (const float*)d_in[4];
    const float* Wk = (const float*)d_in[5];
    const float* bk = (const float*)d_in[6];
    const float* Wv = (const float*)d_in[7];
    const float* bv = (const float*)d_in[8];
    float* out = (float*)d_out;

    float *dq, *dk, *dv;
    cudaGetSymbolAddress((void**)&dq, g_wq);
    cudaGetSymbolAddress((void**)&dk, g_wk);
    cudaGetSymbolAddress((void**)&dv, g_wv);

    dim3 pgrid(DM / 64, M_TOTAL / 128, 3);     // (12, 64, 3)
    proj_fused_kernel<<<pgrid, 256>>>(q, k, v, Wq, bq, Wk, bk, Wv, bv, dq, dk, dv);

    dim3 agrid(SEQ / 64, NH, BATCH);           // (32, 12, 4)
    flash_mma_kernel<<<agrid, 128>>>(dq, dk, dv, out);
}

// round 8
// speedup vs baseline: 4.0824x; 1.3790x over previous
#include <cuda_runtime.h>
#include <cstdint>

#define SEQ   2048
#define DM    768
#define NH    12
#define DH    64
#define BATCH 4
#define M_TOTAL (BATCH * SEQ)   // 8192

// Head-split projection scratch: [b, h, s, d] fp32
__device__ float g_wq[BATCH * NH * SEQ * DH];
__device__ float g_wk[BATCH * NH * SEQ * DH];
__device__ float g_wv[BATCH * NH * SEQ * DH];

// ---------------------------------------------------------------------------
// Precision helpers.
//  - tf32 single-pass operands (P, V): RN via +0x1000 (HW truncates low 13).
//  - bf16 3-term split for score/proj paths: hi = RN_bf16(x), lo = RN_bf16(x-hi).
//    hi+lo reconstructs x to ~2^-18; dropped lo*lo term ~2^-18 per product.
// ---------------------------------------------------------------------------
__device__ __forceinline__ uint32_t rn_bits(float x) {
    return __float_as_uint(x) + 0x1000u;
}
// pack (even,odd) floats -> bf16x2 (low half = even)
__device__ __forceinline__ uint32_t pack_bf16(float e, float o) {
    uint32_t r;
    asm("cvt.rn.bf16x2.f32 %0, %1, %2;" : "=r"(r) : "f"(o), "f"(e));
    return r;
}
// split float2 (even,odd) into hi/lo bf16x2 pair
__device__ __forceinline__ void bf_split(float e, float o, uint32_t& h, uint32_t& l) {
    h = pack_bf16(e, o);
    float he = __uint_as_float(h << 16);
    float ho = __uint_as_float(h & 0xFFFF0000u);
    l = pack_bf16(e - he, o - ho);
}

// m16n8k8 tf32 mma, C += A*B
__device__ __forceinline__ void mma8(float* c,
                                     uint32_t a0, uint32_t a1, uint32_t a2, uint32_t a3,
                                     uint32_t b0, uint32_t b1) {
    asm volatile(
        "mma.sync.aligned.m16n8k8.row.col.f32.tf32.tf32.f32 "
        "{%0,%1,%2,%3}, {%4,%5,%6,%7}, {%8,%9}, {%0,%1,%2,%3};\n"
        : "+f"(c[0]), "+f"(c[1]), "+f"(c[2]), "+f"(c[3])
        : "r"(a0), "r"(a1), "r"(a2), "r"(a3), "r"(b0), "r"(b1));
}
// m16n8k16 bf16 mma, C += A*B
__device__ __forceinline__ void mma16(float* c,
                                      uint32_t a0, uint32_t a1, uint32_t a2, uint32_t a3,
                                      uint32_t b0, uint32_t b1) {
    asm volatile(
        "mma.sync.aligned.m16n8k16.row.col.f32.bf16.bf16.f32 "
        "{%0,%1,%2,%3}, {%4,%5,%6,%7}, {%8,%9}, {%0,%1,%2,%3};\n"
        : "+f"(c[0]), "+f"(c[1]), "+f"(c[2]), "+f"(c[3])
        : "r"(a0), "r"(a1), "r"(a2), "r"(a3), "r"(b0), "r"(b1));
}

// cp.async 16B, L1-bypass
__device__ __forceinline__ void cp16(uint32_t smem_addr, const void* gptr) {
    asm volatile("cp.async.cg.shared.global [%0], [%1], 16;\n"
                 :: "r"(smem_addr), "l"(gptr));
}
__device__ __forceinline__ void cp_commit() {
    asm volatile("cp.async.commit_group;\n");
}

// ---------------------------------------------------------------------------
// Fused projection GEMM: z in {0,1,2} selects (Q,K,V).
// BM=128, BN=64, BK=16. 256 threads = 8 warps (4m x 2n), warp tile 32x32.
// Q/K: 3x bf16-k16 split mma. V: single-pass RN tf32 (precision).
// Double-buffered cp.async staging.
// ---------------------------------------------------------------------------
__global__ __launch_bounds__(256) void proj_fused_kernel(
    const float* __restrict__ Xq, const float* __restrict__ Xk, const float* __restrict__ Xv,
    const float* __restrict__ Wq, const float* __restrict__ bq,
    const float* __restrict__ Wk, const float* __restrict__ bk,
    const float* __restrict__ Wv, const float* __restrict__ bv,
    float* __restrict__ Oq, float* __restrict__ Ok, float* __restrict__ Ov)
{
    const int z = blockIdx.z;
    const float* X    = (z == 0) ? Xq : (z == 1) ? Xk : Xv;
    const float* W    = (z == 0) ? Wq : (z == 1) ? Wk : Wv;
    const float* bias = (z == 0) ? bq : (z == 1) ? bk : bv;
    float* Out        = (z == 0) ? Oq : (z == 1) ? Ok : Ov;
    const bool PRECISE = (z != 2);

    __shared__ float Xs[2][128][24];   // stride 24: conflict-free float2 reads
    __shared__ float Ws[2][64][24];

    const int tid  = threadIdx.x;
    const int lane = tid & 31;
    const int warp = tid >> 5;
    const int wm   = warp & 3;
    const int wn   = warp >> 2;
    const int bm   = blockIdx.y * 128;
    const int bn   = blockIdx.x * 64;

    const int g  = lane >> 2;
    const int tg = lane & 3;

    float acc[2][4][4];
#pragma unroll
    for (int i = 0; i < 2; i++)
#pragma unroll
        for (int j = 0; j < 4; j++)
#pragma unroll
            for (int r = 0; r < 4; r++) acc[i][j][r] = 0.f;

    const uint32_t xs_base = (uint32_t)__cvta_generic_to_shared(&Xs[0][0][0]);
    const uint32_t ws_base = (uint32_t)__cvta_generic_to_shared(&Ws[0][0][0]);
    const int xrow0 = tid >> 2,  xc0 = (tid & 3) * 4;
    const int wrow  = tid >> 2,  wc  = (tid & 3) * 4;

    const int NT = DM / 16;   // 48

    auto issue = [&](int kt) {
        const int k0 = kt * 16;
        const uint32_t xb = xs_base + (uint32_t)((kt & 1) * 128 * 24 * 4);
        const uint32_t wb = ws_base + (uint32_t)((kt & 1) * 64 * 24 * 4);
        cp16(xb + (uint32_t)((xrow0      ) * 24 + xc0) * 4,
             X + (size_t)(bm + xrow0) * DM + k0 + xc0);
        cp16(xb + (uint32_t)((xrow0 + 64 ) * 24 + xc0) * 4,
             X + (size_t)(bm + xrow0 + 64) * DM + k0 + xc0);
        cp16(wb + (uint32_t)(wrow * 24 + wc) * 4,
             W + (size_t)(bn + wrow) * DM + k0 + wc);
        cp_commit();
    };

    issue(0);
    issue(1);

    for (int kt = 0; kt < NT; kt++) {
        if (kt + 1 < NT) asm volatile("cp.async.wait_group 1;\n");
        else             asm volatile("cp.async.wait_group 0;\n");
        __syncthreads();
        const int buf = kt & 1;

        if (PRECISE) {
            // one bf16 k16 step covers BK=16
            uint32_t ah[2][4], al[2][4], bh[4][2], bl[4][2];
#pragma unroll
            for (int mt = 0; mt < 2; mt++) {
                const int rb = wm * 32 + mt * 16;
                float2 A0 = *reinterpret_cast<const float2*>(&Xs[buf][rb + g    ][2 * tg]);
                float2 A1 = *reinterpret_cast<const float2*>(&Xs[buf][rb + g + 8][2 * tg]);
                float2 A2 = *reinterpret_cast<const float2*>(&Xs[buf][rb + g    ][2 * tg + 8]);
                float2 A3 = *reinterpret_cast<const float2*>(&Xs[buf][rb + g + 8][2 * tg + 8]);
                bf_split(A0.x, A0.y, ah[mt][0], al[mt][0]);
                bf_split(A1.x, A1.y, ah[mt][1], al[mt][1]);
                bf_split(A2.x, A2.y, ah[mt][2], al[mt][2]);
                bf_split(A3.x, A3.y, ah[mt][3], al[mt][3]);
            }
#pragma unroll
            for (int nt = 0; nt < 4; nt++) {
                const int nb = wn * 32 + nt * 8;
                float2 B0 = *reinterpret_cast<const float2*>(&Ws[buf][nb + g][2 * tg]);
                float2 B1 = *reinterpret_cast<const float2*>(&Ws[buf][nb + g][2 * tg + 8]);
                bf_split(B0.x, B0.y, bh[nt][0], bl[nt][0]);
                bf_split(B1.x, B1.y, bh[nt][1], bl[nt][1]);
            }
#pragma unroll
            for (int mt = 0; mt < 2; mt++)
#pragma unroll
                for (int nt = 0; nt < 4; nt++) {
                    mma16(acc[mt][nt], ah[mt][0], ah[mt][1], ah[mt][2], ah[mt][3],
                          bh[nt][0], bh[nt][1]);
                    mma16(acc[mt][nt], ah[mt][0], ah[mt][1], ah[mt][2], ah[mt][3],
                          bl[nt][0], bl[nt][1]);
                    mma16(acc[mt][nt], al[mt][0], al[mt][1], al[mt][2], al[mt][3],
                          bh[nt][0], bh[nt][1]);
                }
        } else {
            // V path: tf32 single-pass RN, two k8 steps
#pragma unroll
            for (int ks = 0; ks < 2; ks++) {
                const int kk = ks * 8;
                uint32_t ah[2][4], bh[4][2];
#pragma unroll
                for (int mt = 0; mt < 2; mt++) {
                    const int rb = wm * 32 + mt * 16;
                    ah[mt][0] = rn_bits(Xs[buf][rb + g    ][kk + tg]);
                    ah[mt][1] = rn_bits(Xs[buf][rb + g + 8][kk + tg]);
                    ah[mt][2] = rn_bits(Xs[buf][rb + g    ][kk + tg + 4]);
                    ah[mt][3] = rn_bits(Xs[buf][rb + g + 8][kk + tg + 4]);
                }
#pragma unroll
                for (int nt = 0; nt < 4; nt++) {
                    const int nb = wn * 32 + nt * 8;
                    bh[nt][0] = rn_bits(Ws[buf][nb + g][kk + tg]);
                    bh[nt][1] = rn_bits(Ws[buf][nb + g][kk + tg + 4]);
                }
#pragma unroll
                for (int mt = 0; mt < 2; mt++)
#pragma unroll
                    for (int nt = 0; nt < 4; nt++)
                        mma8(acc[mt][nt], ah[mt][0], ah[mt][1], ah[mt][2], ah[mt][3],
                             bh[nt][0], bh[nt][1]);
            }
        }
        __syncthreads();
        if (kt + 2 < NT) issue(kt + 2);
    }

    // Epilogue: add bias, scatter into head-split layout [b, h, s, d]
#pragma unroll
    for (int mt = 0; mt < 2; mt++) {
#pragma unroll
        for (int nt = 0; nt < 4; nt++) {
            const int n  = bn + wn * 32 + nt * 8 + 2 * tg;
            const int h  = n / DH;
            const int d  = n % DH;
            const float b0 = bias[n];
            const float b1 = bias[n + 1];
#pragma unroll
            for (int rr = 0; rr < 2; rr++) {
                const int m = bm + wm * 32 + mt * 16 + g + rr * 8;
                const int bb = m / SEQ;
                const int s  = m % SEQ;
                float2 v;
                v.x = acc[mt][nt][rr * 2 + 0] + b0;
                v.y = acc[mt][nt][rr * 2 + 1] + b1;
                *reinterpret_cast<float2*>(
                    Out + (((size_t)(bb * NH + h)) * SEQ + s) * DH + d) = v;
            }
        }
    }
}

// ---------------------------------------------------------------------------
// Flash attention. 64 q rows/block, 4 warps, key tiles of 32, double-buffered
// cp.async. Scores: 3x bf16-k16 (Q split hoisted to regs, K split in-register
// from float2 LDS). PV: single-pass RN tf32.
// ---------------------------------------------------------------------------
__global__ __launch_bounds__(128, 4) void flash_mma_kernel(
    const float* __restrict__ Qh,
    const float* __restrict__ Kh,
    const float* __restrict__ Vh,
    float* __restrict__ out)
{
    __shared__ float Ks[2][32][72];    // raw K; stride 72: conflict-free f2 reads
    __shared__ float Vs[2][32][72];    // raw V
    __shared__ float Ps[4][16][36];    // per-warp P tile (pre-rounded bits)

    const int tid  = threadIdx.x;
    const int lane = tid & 31;
    const int warp = tid >> 5;
    const int g    = lane >> 2;
    const int tg   = lane & 3;

    const int b  = blockIdx.z;
    const int h  = blockIdx.y;
    const int q0 = blockIdx.x * 64;
    const size_t base = ((size_t)(b * NH + h)) * SEQ * DH;

    const uint32_t ks_base = (uint32_t)__cvta_generic_to_shared(&Ks[0][0][0]);
    const uint32_t vs_base = (uint32_t)__cvta_generic_to_shared(&Vs[0][0][0]);

    auto issue = [&](int kt) {
        const uint32_t kb = ks_base + (uint32_t)((kt & 1) * 32 * 72 * 4);
        const uint32_t vb = vs_base + (uint32_t)((kt & 1) * 32 * 72 * 4);
        const float* kp = Kh + base + (size_t)(kt * 32) * DH;
        const float* vp = Vh + base + (size_t)(kt * 32) * DH;
#pragma unroll
        for (int i = 0; i < 4; i++) {
            const int idx = i * 128 + tid;
            const int row = idx >> 4;
            const int c   = (idx & 15) * 4;
            cp16(kb + (uint32_t)(row * 72 + c) * 4, kp + row * 64 + c);
            cp16(vb + (uint32_t)(row * 72 + c) * 4, vp + row * 64 + c);
        }
        cp_commit();
    };

    // Hoisted Q fragments (bf16 hi/lo): 4 ksteps x 4 regs each
    uint32_t qh[4][4], ql[4][4];
    {
        const float* q0p = Qh + base + (size_t)(q0 + warp * 16 + g) * DH;
        const float* q1p = q0p + 8 * DH;
#pragma unroll
        for (int s = 0; s < 4; s++) {
            const int c0 = s * 16 + 2 * tg;
            float2 A0 = *reinterpret_cast<const float2*>(q0p + c0);
            float2 A1 = *reinterpret_cast<const float2*>(q1p + c0);
            float2 A2 = *reinterpret_cast<const float2*>(q0p + c0 + 8);
            float2 A3 = *reinterpret_cast<const float2*>(q1p + c0 + 8);
            bf_split(A0.x, A0.y, qh[s][0], ql[s][0]);
            bf_split(A1.x, A1.y, qh[s][1], ql[s][1]);
            bf_split(A2.x, A2.y, qh[s][2], ql[s][2]);
            bf_split(A3.x, A3.y, qh[s][3], ql[s][3]);
        }
    }

    issue(0);
    issue(1);

    float oacc[8][4];
#pragma unroll
    for (int dt = 0; dt < 8; dt++)
#pragma unroll
        for (int r = 0; r < 4; r++) oacc[dt][r] = 0.f;
    float mrow0 = -1e30f, mrow1 = -1e30f;
    float lrow0 = 0.f,    lrow1 = 0.f;

    const int NT = SEQ / 32;   // 64

    for (int kt = 0; kt < NT; kt++) {
        if (kt + 1 < NT) asm volatile("cp.async.wait_group 1;\n");
        else             asm volatile("cp.async.wait_group 0;\n");
        __syncthreads();
        const int buf = kt & 1;

        // Scores: S (16 x 32) per warp, 3x bf16-k16
        float sacc[4][4];
#pragma unroll
        for (int nt = 0; nt < 4; nt++)
#pragma unroll
            for (int r = 0; r < 4; r++) sacc[nt][r] = 0.f;

#pragma unroll
        for (int s = 0; s < 4; s++) {
            const int c0 = s * 16 + 2 * tg;
#pragma unroll
            for (int nt = 0; nt < 4; nt++) {
                float2 K0 = *reinterpret_cast<const float2*>(&Ks[buf][nt * 8 + g][c0]);
                float2 K1 = *reinterpret_cast<const float2*>(&Ks[buf][nt * 8 + g][c0 + 8]);
                uint32_t bh0, bl0, bh1, bl1;
                bf_split(K0.x, K0.y, bh0, bl0);
                bf_split(K1.x, K1.y, bh1, bl1);
                mma16(sacc[nt], qh[s][0], qh[s][1], qh[s][2], qh[s][3], bh0, bh1);
                mma16(sacc[nt], qh[s][0], qh[s][1], qh[s][2], qh[s][3], bl0, bl1);
                mma16(sacc[nt], ql[s][0], ql[s][1], ql[s][2], ql[s][3], bh0, bh1);
            }
        }

        // Online softmax (rows g and g+8 of this warp's 16-row strip)
        float tmax0 = sacc[0][0], tmax1 = sacc[0][2];
#pragma unroll
        for (int nt = 0; nt < 4; nt++) {
            tmax0 = fmaxf(tmax0, fmaxf(sacc[nt][0], sacc[nt][1]));
            tmax1 = fmaxf(tmax1, fmaxf(sacc[nt][2], sacc[nt][3]));
        }
        tmax0 = fmaxf(tmax0, __shfl_xor_sync(0xffffffff, tmax0, 1));
        tmax0 = fmaxf(tmax0, __shfl_xor_sync(0xffffffff, tmax0, 2));
        tmax1 = fmaxf(tmax1, __shfl_xor_sync(0xffffffff, tmax1, 1));
        tmax1 = fmaxf(tmax1, __shfl_xor_sync(0xffffffff, tmax1, 2));

        const float mnew0 = fmaxf(mrow0, tmax0);
        const float mnew1 = fmaxf(mrow1, tmax1);
        const float corr0 = __expf(mrow0 - mnew0);
        const float corr1 = __expf(mrow1 - mnew1);
        mrow0 = mnew0; mrow1 = mnew1;

        float ps0 = 0.f, ps1 = 0.f;
#pragma unroll
        for (int nt = 0; nt < 4; nt++) {
            sacc[nt][0] = __expf(sacc[nt][0] - mnew0);
            sacc[nt][1] = __expf(sacc[nt][1] - mnew0);
            sacc[nt][2] = __expf(sacc[nt][2] - mnew1);
            sacc[nt][3] = __expf(sacc[nt][3] - mnew1);
            ps0 += sacc[nt][0] + sacc[nt][1];
            ps1 += sacc[nt][2] + sacc[nt][3];
        }
        ps0 += __shfl_xor_sync(0xffffffff, ps0, 1);
        ps0 += __shfl_xor_sync(0xffffffff, ps0, 2);
        ps1 += __shfl_xor_sync(0xffffffff, ps1, 1);
        ps1 += __shfl_xor_sync(0xffffffff, ps1, 2);
        lrow0 = lrow0 * corr0 + ps0;
        lrow1 = lrow1 * corr1 + ps1;

#pragma unroll
        for (int dt = 0; dt < 8; dt++) {
            oacc[dt][0] *= corr0;
            oacc[dt][1] *= corr0;
            oacc[dt][2] *= corr1;
            oacc[dt][3] *= corr1;
        }

        // P tile to per-warp smem, pre-rounded (RN after HW trunc)
#pragma unroll
        for (int nt = 0; nt < 4; nt++) {
            const int col = nt * 8 + 2 * tg;
            *reinterpret_cast<uint2*>(&Ps[warp][g][col]) =
                make_uint2(rn_bits(sacc[nt][0]), rn_bits(sacc[nt][1]));
            *reinterpret_cast<uint2*>(&Ps[warp][g + 8][col]) =
                make_uint2(rn_bits(sacc[nt][2]), rn_bits(sacc[nt][3]));
        }
        __syncwarp();

        // PV: O(16x64) += P(16x32) @ V(32x64); tf32 single-pass, V RN at consume
#pragma unroll
        for (int kk = 0; kk < 4; kk++) {
            const int kc = kk * 8;
            uint32_t a0 = __float_as_uint(Ps[warp][g][kc + tg]);
            uint32_t a1 = __float_as_uint(Ps[warp][g + 8][kc + tg]);
            uint32_t a2 = __float_as_uint(Ps[warp][g][kc + tg + 4]);
            uint32_t a3 = __float_as_uint(Ps[warp][g + 8][kc + tg + 4]);
#pragma unroll
            for (int dt = 0; dt < 8; dt++) {
                uint32_t b0 = __float_as_uint(Vs[buf][kc + tg][dt * 8 + g]) + 0x1000u;
                uint32_t b1 = __float_as_uint(Vs[buf][kc + tg + 4][dt * 8 + g]) + 0x1000u;
                mma8(oacc[dt], a0, a1, a2, a3, b0, b1);
            }
        }

        __syncthreads();
        if (kt + 2 < NT) issue(kt + 2);
    }

    // Epilogue: normalize + write merged-head output [b, s, h*64 + d]
    const float inv0 = 1.f / lrow0;
    const float inv1 = 1.f / lrow1;
    const int row0 = q0 + warp * 16 + g;
    const int row1 = row0 + 8;
    float* o0 = out + ((size_t)(b * SEQ + row0)) * DM + h * DH;
    float* o1 = out + ((size_t)(b * SEQ + row1)) * DM + h * DH;
#pragma unroll
    for (int dt = 0; dt < 8; dt++) {
        const int col = dt * 8 + 2 * tg;
        float2 v0, v1;
        v0.x = oacc[dt][0] * inv0; v0.y = oacc[dt][1] * inv0;
        v1.x = oacc[dt][2] * inv1; v1.y = oacc[dt][3] * inv1;
        *reinterpret_cast<float2*>(o0 + col) = v0;
        *reinterpret_cast<float2*>(o1 + col) = v1;
    }
}

// ---------------------------------------------------------------------------
// Launch
// ---------------------------------------------------------------------------
extern "C" void kernel_launch(void* const* d_in, const int* in_sizes, int n_in,
                              void* d_out, int out_size)
{
    const float* q  = (const float*)d_in[0];
    const float* k  = (const float*)d_in[1];
    const float* v  = (const float*)d_in[2];
    const float* Wq = (const float*)d_in[3];
    const float* bq = (const float*)d_in[4];
    const float* Wk = (const float*)d_in[5];
    const float* bk = (const float*)d_in[6];
    const float* Wv = (const float*)d_in[7];
    const float* bv = (const float*)d_in[8];
    float* out = (float*)d_out;

    float *dq, *dk, *dv;
    cudaGetSymbolAddress((void**)&dq, g_wq);
    cudaGetSymbolAddress((void**)&dk, g_wk);
    cudaGetSymbolAddress((void**)&dv, g_wv);

    dim3 pgrid(DM / 64, M_TOTAL / 128, 3);     // (12, 64, 3)
    proj_fused_kernel<<<pgrid, 256>>>(q, k, v, Wq, bq, Wk, bk, Wv, bv, dq, dk, dv);

    dim3 agrid(SEQ / 64, NH, BATCH);           // (32, 12, 4)
    flash_mma_kernel<<<agrid, 128>>>(dq, dk, dv, out);
}